// round 11
// baseline (speedup 1.0000x reference)
#include <cuda_runtime.h>
#include <cstdint>
#include <cfloat>

// Problem constants (StyleCodebook: B=16, N=4096, D=256, K=512)
static constexpr int TOKENS = 65536;
static constexpr int D      = 256;   // GEMM K
static constexpr int K      = 512;   // codes = GEMM N

static constexpr int BM  = 128;      // tokens per CTA
static constexpr int BN  = 128;      // codes per N-chunk
static constexpr int NKCH = 8;       // K-chunks of 32
static constexpr int NNCH = 4;       // N-chunks
static constexpr int NIT  = NKCH * NNCH;  // 32 pipeline iterations
static constexpr int STG  = 3;       // pipeline stages

// dynamic smem: esq | 3 stages x (A raw 16KB + Bhi 16KB + Blo 16KB)
static constexpr int SM_ESQ = 0;
#define SM_A(s)  (2048 + (s) * 49152)
#define SM_BH(s) (SM_A(s) + 16384)
#define SM_BL(s) (SM_A(s) + 32768)
static constexpr int SMEM_TOTAL = 2048 + STG * 49152;  // 149504
// epilogue scratch (reuses pipeline smem)
static constexpr int SM_REDD = SM_A(0);
static constexpr int SM_REDI = SM_A(0) + 2048;
static constexpr int SM_IDX  = SM_A(0) + 4096;

#define SWZ128(o) ((o) ^ ((((unsigned)(o)) >> 3) & 0x70))

// Scratch (device globals; no allocation allowed)
__device__ float g_cbhi[K * D];
__device__ float g_cblo[K * D];
__device__ float g_partial[TOKENS / BM];   // one partial per argmin CTA (512)
__device__ float g_esq[K];

__device__ __forceinline__ uint32_t smem_u32(const void* p) {
    uint32_t a;
    asm("{ .reg .u64 t; cvta.to.shared.u64 t, %1; cvt.u32.u64 %0, t; }"
        : "=r"(a) : "l"(p));
    return a;
}

__device__ __forceinline__ float tf32_rn(float x) {
    uint32_t r;
    asm("cvt.rna.tf32.f32 %0, %1;" : "=r"(r) : "f"(x));
    return __uint_as_float(r);
}

#define CP_ASYNC16(dst, src)                                                  \
    asm volatile("cp.async.cg.shared.global [%0], [%1], 16;"                  \
                 :: "r"(dst), "l"(src))
#define CP_COMMIT() asm volatile("cp.async.commit_group;")
#define CP_WAIT(n)  asm volatile("cp.async.wait_group %0;" :: "n"(n))

#define LDSM_X4(r0, r1, r2, r3, addr)                                         \
    asm volatile(                                                             \
        "ldmatrix.sync.aligned.m8n8.x4.shared.b16 {%0,%1,%2,%3}, [%4];"       \
        : "=r"(r0), "=r"(r1), "=r"(r2), "=r"(r3) : "r"(addr))

#define MMA_TF32(d, a, b)                                                     \
    asm volatile(                                                             \
        "mma.sync.aligned.m16n8k8.row.col.f32.tf32.tf32.f32 "                 \
        "{%0,%1,%2,%3}, {%4,%5,%6,%7}, {%8,%9}, {%0,%1,%2,%3};"               \
        : "+f"((d)[0]), "+f"((d)[1]), "+f"((d)[2]), "+f"((d)[3])              \
        : "r"((a)[0]), "r"((a)[1]), "r"((a)[2]), "r"((a)[3]),                 \
          "r"((b)[0]), "r"((b)[1]))

// ---------------------------------------------------------------------------
// Kernel 0: pre-split codebook into tf32 hi (rna) + raw lo, and row norms.
// Numerically identical to the in-loop split it replaces.
// ---------------------------------------------------------------------------
__global__ void split_cb_kernel(const float* __restrict__ cb) {
    const int k = blockIdx.x;        // code row
    const int d = threadIdx.x;       // D threads
    const float v = cb[(size_t)k * D + d];
    const float h = tf32_rn(v);
    g_cbhi[(size_t)k * D + d] = h;
    g_cblo[(size_t)k * D + d] = v - h;

    float s = v * v;
    #pragma unroll
    for (int o = 16; o > 0; o >>= 1) s += __shfl_down_sync(0xffffffffu, s, o);
    __shared__ float ws[8];
    if ((d & 31) == 0) ws[d >> 5] = s;
    __syncthreads();
    if (d == 0) {
        float tot = 0.f;
        #pragma unroll
        for (int w = 0; w < 8; ++w) tot += ws[w];
        g_esq[k] = tot;
    }
}

// ---------------------------------------------------------------------------
// cp.async staging of one (nch, kch) chunk into buffer it%STG
// A raw fp32; B pre-split hi/lo.
// ---------------------------------------------------------------------------
__device__ __forceinline__ void stage_chunk(const float* __restrict__ z,
                                            uint32_t sb, int tid, int it, int m0) {
    const int nch = it >> 3, kch = it & 7, buf = it % STG;
    const uint32_t aB  = sb + SM_A(buf);
    const uint32_t bhB = sb + SM_BH(buf);
    const uint32_t blB = sb + SM_BL(buf);
    #pragma unroll
    for (int j = 0; j < 4; ++j) {
        int i   = j * 256 + tid;
        int row = i >> 3, seg = i & 7;
        unsigned off = SWZ128(row * 128 + seg * 16);
        const float* sA = z + (size_t)(m0 + row) * D + kch * 32 + seg * 4;
        CP_ASYNC16(aB + off, (size_t)__cvta_generic_to_global(sA));
        const size_t bix = (size_t)(nch * BN + row) * D + kch * 32 + seg * 4;
        CP_ASYNC16(bhB + off, (size_t)__cvta_generic_to_global(g_cbhi + bix));
        CP_ASYNC16(blB + off, (size_t)__cvta_generic_to_global(g_cblo + bix));
    }
}

// ---------------------------------------------------------------------------
// Compute one chunk: A split in regs; B frags MMA-ready from smem. 3xTF32.
// ---------------------------------------------------------------------------
__device__ __forceinline__ void compute_chunk(uint32_t aBase, uint32_t bhBase,
                                              uint32_t blBase,
                                              float (&acc)[4][4][4],
                                              int warpM, int warpN,
                                              int rowInMat, int segSel) {
    #pragma unroll
    for (int kk = 0; kk < 4; ++kk) {
        const int seg = kk * 2 + segSel;

        uint32_t ahf[4][4], alf[4][4];
        #pragma unroll
        for (int mt = 0; mt < 4; ++mt) {
            int row = warpM * 64 + mt * 16 + rowInMat;
            unsigned off = (unsigned)(row * 128 + ((seg ^ (row & 7)) << 4));
            uint32_t r0, r1, r2, r3;
            LDSM_X4(r0, r1, r2, r3, aBase + off);
            uint32_t raw[4] = {r0, r1, r2, r3};
            #pragma unroll
            for (int q = 0; q < 4; ++q) {
                float v = __uint_as_float(raw[q]);
                float h = tf32_rn(v);
                ahf[mt][q] = __float_as_uint(h);
                alf[mt][q] = __float_as_uint(v - h);   // raw lo, HW-truncated
            }
        }

        uint32_t bhf[4][2], blf[4][2];
        #pragma unroll
        for (int p = 0; p < 2; ++p) {
            int row = warpN * 32 + p * 16 + rowInMat;
            unsigned off = (unsigned)(row * 128 + ((seg ^ (row & 7)) << 4));
            uint32_t r0, r1, r2, r3;
            LDSM_X4(r0, r1, r2, r3, bhBase + off);
            bhf[2 * p][0] = r0; bhf[2 * p][1] = r2;
            bhf[2 * p + 1][0] = r1; bhf[2 * p + 1][1] = r3;
            LDSM_X4(r0, r1, r2, r3, blBase + off);
            blf[2 * p][0] = r0; blf[2 * p][1] = r2;
            blf[2 * p + 1][0] = r1; blf[2 * p + 1][1] = r3;
        }

        #pragma unroll
        for (int mt = 0; mt < 4; ++mt)
            #pragma unroll
            for (int nt = 0; nt < 4; ++nt)
                MMA_TF32(acc[mt][nt], ahf[mt], bhf[nt]);   // hi*hi
        #pragma unroll
        for (int mt = 0; mt < 4; ++mt)
            #pragma unroll
            for (int nt = 0; nt < 4; ++nt)
                MMA_TF32(acc[mt][nt], ahf[mt], blf[nt]);   // hi*lo
        #pragma unroll
        for (int mt = 0; mt < 4; ++mt)
            #pragma unroll
            for (int nt = 0; nt < 4; ++nt)
                MMA_TF32(acc[mt][nt], alf[mt], bhf[nt]);   // lo*hi
    }
}

// ---------------------------------------------------------------------------
// Kernel 1: pipelined tf32 z@cb^T + argmin + fused gather/quantize/loss
// dist(k) = ||e_k||^2 - 2*dot  (z^2 constant per token)
// ---------------------------------------------------------------------------
__global__ void __launch_bounds__(256, 1)
argmin_mma_kernel(const float* __restrict__ z,
                  const unsigned* __restrict__ mask,
                  const float* __restrict__ cb,
                  float* __restrict__ outQ,
                  float* __restrict__ outI) {
    extern __shared__ char smem[];
    const uint32_t sb = smem_u32(smem);
    float* esq_s = reinterpret_cast<float*>(smem + SM_ESQ);

    const int tid   = threadIdx.x;
    const int lane  = tid & 31;
    const int warp  = tid >> 5;
    const int warpM = warp >> 2;
    const int warpN = warp & 3;
    const int m0    = blockIdx.x * BM;

    const int matIdx   = lane >> 3;
    const int rowInMat = (lane & 7) + (matIdx & 1) * 8;
    const int segSel   = matIdx >> 1;

    for (int i = tid; i < K; i += 256) esq_s[i] = g_esq[i];

    float bestD[8];
    int   bestI[8];
    #pragma unroll
    for (int b = 0; b < 8; ++b) { bestD[b] = FLT_MAX; bestI[b] = 0; }

    // Pipeline prologue: chunks 0, 1 in flight
    stage_chunk(z, sb, tid, 0, m0); CP_COMMIT();
    stage_chunk(z, sb, tid, 1, m0); CP_COMMIT();

    for (int nch = 0; nch < NNCH; ++nch) {
        float acc[4][4][4];
        #pragma unroll
        for (int mt = 0; mt < 4; ++mt)
            #pragma unroll
            for (int nt = 0; nt < 4; ++nt)
                #pragma unroll
                for (int r = 0; r < 4; ++r) acc[mt][nt][r] = 0.f;

        for (int kch = 0; kch < NKCH; ++kch) {
            const int it = nch * NKCH + kch;
            // Buffer (it+2)%3 was last READ at iteration it-1; this barrier
            // separates those reads from the new cp.async writes below.
            if (it == NIT - 1) { CP_WAIT(0); } else { CP_WAIT(1); }
            __syncthreads();
            if (it + 2 < NIT) {
                stage_chunk(z, sb, tid, it + 2, m0);
                CP_COMMIT();
            }
            const int buf = it % STG;
            compute_chunk(sb + SM_A(buf), sb + SM_BH(buf), sb + SM_BL(buf),
                          acc, warpM, warpN, rowInMat, segSel);
        }

        // Running argmin (codes ascending across nch/nt/col: strict '<'
        // keeps the earliest index, matching jnp.argmin tie semantics)
        #pragma unroll
        for (int mt = 0; mt < 4; ++mt)
            #pragma unroll
            for (int half = 0; half < 2; ++half) {
                const int b = mt * 2 + half;
                #pragma unroll
                for (int nt = 0; nt < 4; ++nt) {
                    int code = nch * BN + warpN * 32 + nt * 8 + 2 * (lane & 3);
                    float d0 = esq_s[code]     - 2.f * acc[mt][nt][half * 2];
                    float d1 = esq_s[code + 1] - 2.f * acc[mt][nt][half * 2 + 1];
                    if (d0 < bestD[b]) { bestD[b] = d0; bestI[b] = code; }
                    if (d1 < bestD[b]) { bestD[b] = d1; bestI[b] = code + 1; }
                }
            }
    }

    // Quad reduction (threads in a quad share the same token row)
    #pragma unroll
    for (int b = 0; b < 8; ++b) {
        float d = bestD[b]; int i = bestI[b];
        #pragma unroll
        for (int off = 1; off < 4; off <<= 1) {
            float d2 = __shfl_xor_sync(0xffffffffu, d, off);
            int   i2 = __shfl_xor_sync(0xffffffffu, i, off);
            if (d2 < d || (d2 == d && i2 < i)) { d = d2; i = i2; }
        }
        bestD[b] = d; bestI[b] = i;
    }

    __syncthreads();   // compute done; reuse pipeline smem
    float* redD = reinterpret_cast<float*>(smem + SM_REDD);
    int*   redI = reinterpret_cast<int*>(smem + SM_REDI);
    int*   idxs = reinterpret_cast<int*>(smem + SM_IDX);
    if ((lane & 3) == 0) {
        const int g = lane >> 2;
        #pragma unroll
        for (int mt = 0; mt < 4; ++mt)
            #pragma unroll
            for (int half = 0; half < 2; ++half) {
                int row = warpM * 64 + mt * 16 + half * 8 + g;
                redD[warpN * BM + row] = bestD[mt * 2 + half];
                redI[warpN * BM + row] = bestI[mt * 2 + half];
            }
    }
    __syncthreads();
    if (tid < BM) {
        float bd = redD[tid];
        int   bi = redI[tid];
        #pragma unroll
        for (int w = 1; w < 4; ++w) {
            float d2 = redD[w * BM + tid];
            int   i2 = redI[w * BM + tid];
            if (d2 < bd || (d2 == bd && i2 < bi)) { bd = d2; bi = i2; }
        }
        idxs[tid] = bi;
    }
    __syncthreads();

    // Fused gather + quantized/indices writes + per-CTA loss partial.
    // Warp w handles tokens [w*16, w*16+16); lane covers 8 of 256 dims.
    __shared__ float ws[8];
    float wsum = 0.f;
    #pragma unroll
    for (int j = 0; j < 16; ++j) {
        const int tloc = warp * 16 + j;
        const int t    = m0 + tloc;
        const int idx  = idxs[tloc];
        const unsigned mw = mask[t];

        const float4* zr = reinterpret_cast<const float4*>(z  + (size_t)t   * D) + lane * 2;
        const float4* er = reinterpret_cast<const float4*>(cb + (size_t)idx * D) + lane * 2;
        float4 z0 = zr[0], z1 = zr[1];
        float4 e0 = er[0], e1 = er[1];

        float4* qw = reinterpret_cast<float4*>(outQ + (size_t)t * D) + lane * 2;
        const float4 zero4 = make_float4(0.f, 0.f, 0.f, 0.f);
        qw[0] = mw ? e0 : zero4;
        qw[1] = mw ? e1 : zero4;

        float s = 0.f, d;
        d = e0.x - z0.x; s += d * d;  d = e0.y - z0.y; s += d * d;
        d = e0.z - z0.z; s += d * d;  d = e0.w - z0.w; s += d * d;
        d = e1.x - z1.x; s += d * d;  d = e1.y - z1.y; s += d * d;
        d = e1.z - z1.z; s += d * d;  d = e1.w - z1.w; s += d * d;
        #pragma unroll
        for (int o = 16; o > 0; o >>= 1) s += __shfl_down_sync(0xffffffffu, s, o);
        if (lane == 0) {
            wsum += s;
            outI[t] = mw ? (float)idx : -1.0f;
        }
    }
    if (lane == 0) ws[warp] = wsum;
    __syncthreads();
    if (tid == 0) {
        float tot = 0.f;
        #pragma unroll
        for (int w = 0; w < 8; ++w) tot += ws[w];
        g_partial[blockIdx.x] = tot;
    }
}

// ---------------------------------------------------------------------------
// Kernel 2: deterministic final loss reduction over 512 CTA partials
// ---------------------------------------------------------------------------
__global__ void loss_kernel(float* __restrict__ outL) {
    __shared__ float sm[256];
    const int tid = threadIdx.x;
    sm[tid] = g_partial[tid] + g_partial[tid + 256];
    __syncthreads();
    #pragma unroll
    for (int s = 128; s > 0; s >>= 1) {
        if (tid < s) sm[tid] += sm[tid + s];
        __syncthreads();
    }
    if (tid == 0)
        outL[0] = 0.25f * sm[0] / (float)((size_t)TOKENS * D);
}

// ---------------------------------------------------------------------------
extern "C" void kernel_launch(void* const* d_in, const int* in_sizes, int n_in,
                              void* d_out, int out_size) {
    const float*    z    = (const float*)d_in[0];
    const unsigned* mask = (const unsigned*)d_in[1];
    const float*    cb   = (const float*)d_in[2];

    float* out  = (float*)d_out;
    float* outQ = out;
    float* outI = out + (size_t)TOKENS * D;
    float* outL = outI + TOKENS;

    cudaFuncSetAttribute(argmin_mma_kernel,
                         cudaFuncAttributeMaxDynamicSharedMemorySize, SMEM_TOTAL);

    split_cb_kernel<<<K, D>>>(cb);
    argmin_mma_kernel<<<TOKENS / BM, 256, SMEM_TOTAL>>>(z, mask, cb, outQ, outI);
    loss_kernel<<<1, 256>>>(outL);
}